// round 13
// baseline (speedup 1.0000x reference)
#include <cuda_runtime.h>
#include <math_constants.h>

#define WSZ    8
#define P2     64
#define CH     128
#define W1G    32
#define NWPB   1024
#define BATCH  8
#define NWIN   (BATCH*NWPB)
#define HD     32
#define NH     4
#define SHIFT  4
#define PSTR   132
#define NTHR   512

// f32 buffer swizzles (for xd and v, float granularity)
__device__ __forceinline__ int swz4(int tok, int c4) { return tok * 32 + (c4 ^ (tok & 7)); }
__device__ __forceinline__ int swz(int tok, int ch) {
    return tok * 128 + ((((ch >> 2) ^ (tok & 7))) << 2) + (ch & 3);
}
// packed-pair buffers: slot = uint2{hi,lo} per channel pair. 64 tok x 64 slots.
__device__ __forceinline__ int upz(int tok, int p) { return tok * 64 + (p ^ (tok & 7)); }
// sim/probs: 64 tok x 32 slots (float2 before softmax, uint2 after)
__device__ __forceinline__ int psl(int i, int p) { return i * 32 + (p ^ (i & 7)); }

// bf16 split helpers
__device__ __forceinline__ float trunc_hi(float x) {
    return __uint_as_float(__float_as_uint(x) & 0xffff0000u);
}
__device__ __forceinline__ unsigned prmt_hi(float a, float b) {
    unsigned r;
    asm("prmt.b32 %0, %1, %2, 0x7632;" : "=r"(r)
        : "r"(__float_as_uint(a)), "r"(__float_as_uint(b)));
    return r;
}
__device__ __forceinline__ unsigned pack_rn(float a, float b) {
    unsigned r;
    asm("cvt.rn.bf16x2.f32 %0, %1, %2;" : "=r"(r) : "f"(b), "f"(a));
    return r;
}
__device__ __forceinline__ uint2 split_pair(float x, float y) {
    uint2 u;
    u.x = prmt_hi(x, y);
    u.y = pack_rn(x - trunc_hi(x), y - trunc_hi(y));
    return u;
}
__device__ __forceinline__ void mma_bf16(float c[4], unsigned a0, unsigned a1,
                                         unsigned a2, unsigned a3,
                                         unsigned b0, unsigned b1) {
    asm volatile(
        "mma.sync.aligned.m16n8k16.row.col.f32.bf16.bf16.f32 "
        "{%0,%1,%2,%3}, {%4,%5,%6,%7}, {%8,%9}, {%0,%1,%2,%3};\n"
        : "+f"(c[0]), "+f"(c[1]), "+f"(c[2]), "+f"(c[3])
        : "r"(a0), "r"(a1), "r"(a2), "r"(a3), "r"(b0), "r"(b1));
}
// 3-term bf16x3 accumulation: Ah*Bh + Al*Bh + Ah*Bl
__device__ __forceinline__ void mma3(float c[4], uint2 a0, uint2 a1, uint2 a2, uint2 a3,
                                     unsigned bh0, unsigned bh1, unsigned bl0, unsigned bl1) {
    mma_bf16(c, a0.x, a1.x, a2.x, a3.x, bh0, bh1);
    mma_bf16(c, a0.y, a1.y, a2.y, a3.y, bh0, bh1);
    mma_bf16(c, a0.x, a1.x, a2.x, a3.x, bl0, bl1);
}

// ---------------- scratch ----------------
__device__ float g_xw [(size_t)NWIN * P2 * CH];          // f32 for blend
__device__ uint2 g_xq [(size_t)NWIN * P2 * 64];          // pre-split xw pairs for q-GEMM
__device__ float g_off[NWIN * P2 * 2];
__device__ float g_oi [NWIN * 2];
// weight fragments: uint4 {bh0,bh1,bl0,bl1}, idx = (n8*8+ks)*32 + lane
__device__ uint4 g_qf[4096], g_kf[4096], g_vf[4096], g_of[4096];

// ---------------- kernel 0: weight fragment prep ----------------
__global__ __launch_bounds__(256)
void k_wfrag(const float* __restrict__ q_w, const float* __restrict__ kv_w,
             const float* __restrict__ o_w)
{
    const int i = blockIdx.x * 256 + threadIdx.x;
    const int lane = i & 31, ks = (i >> 5) & 7, n8 = i >> 8;
    const int n  = n8 * 8 + (lane >> 2);
    const int kb = ks * 16 + (lane & 3) * 2;

    #define DO_FRAG(w, S, O, f) {                                             \
        const float v00 = w[(size_t)(kb    ) * S + O + n];                    \
        const float v01 = w[(size_t)(kb + 1) * S + O + n];                    \
        const float v10 = w[(size_t)(kb + 8) * S + O + n];                    \
        const float v11 = w[(size_t)(kb + 9) * S + O + n];                    \
        f[i] = make_uint4(prmt_hi(v00, v01), prmt_hi(v10, v11),               \
                          pack_rn(v00 - trunc_hi(v00), v01 - trunc_hi(v01)),  \
                          pack_rn(v10 - trunc_hi(v10), v11 - trunc_hi(v11))); \
    }
    DO_FRAG(q_w, 128, 0,   g_qf)
    DO_FRAG(kv_w, 256, 0,   g_kf)
    DO_FRAG(kv_w, 256, 128, g_vf)
    DO_FRAG(o_w, 128, 0,   g_of)
    #undef DO_FRAG
}

// ---------------- kernel 1: window gather + offset MLPs + pre-split ----------------
__global__ __launch_bounds__(256)
void k_prep(const float* __restrict__ x,
            const float* __restrict__ wi_w, const float* __restrict__ wi_b,
            const float* __restrict__ w1_w, const float* __restrict__ w1_b,
            const float* __restrict__ w2_w, const float* __restrict__ w2_b)
{
    __shared__ float sT[P2 * PSTR];
    __shared__ float sT1[P2 * 2];

    const int win = blockIdx.x;
    const int b   = win >> 10;
    const int wr  = win & 1023;
    const int wi  = wr >> 5;
    const int wj  = wr & 31;
    const int tid = threadIdx.x;

    float4* gx4 = (float4*)(g_xw + (size_t)win * P2 * CH);

    for (int i4 = tid; i4 < P2 * CH / 4; i4 += 256) {
        const int tok = i4 >> 5, c4 = i4 & 31;
        const int pi = tok >> 3, pj = tok & 7;
        const int r = (wi * 8 + pi + SHIFT) & 255;
        const int c = (wj * 8 + pj + SHIFT) & 255;
        const float4 v = *(const float4*)(x + (size_t)((((b << 8) + r) << 8) + c) * CH + c4 * 4);
        *(float4*)(sT + tok * PSTR + c4 * 4) = v;
        gx4[i4] = v;
    }
    __syncthreads();

    // pre-split xw pairs for q-GEMM: g_xq[win][tok][p]
    {
        uint2* dst = g_xq + (size_t)win * P2 * 64;
        for (int i = tid; i < P2 * 64; i += 256) {
            const int tok = i >> 6, p = i & 63;
            dst[i] = split_pair(sT[tok * PSTR + 2 * p], sT[tok * PSTR + 2 * p + 1]);
        }
    }

    {
        const int kind = tid >> 7;
        const int rem  = tid & 127;
        const int tok  = rem >> 1;
        const int d    = rem & 1;
        const float* w = kind ? w1_w : wi_w;
        float acc = 0.f;
        #pragma unroll 8
        for (int ch = 0; ch < 128; ++ch)
            acc = fmaf(sT[tok * PSTR + ch], w[ch * 2 + d], acc);
        if (kind) sT1[tok * 2 + d] = acc + w1_b[d];
        else      g_off[win * 128 + tok * 2 + d] = acc + wi_b[d];
    }
    __syncthreads();

    if (tid < 2) {
        float acc = w2_b[tid];
        for (int f = 0; f < 128; ++f)
            acc = fmaf(sT1[f], w2_w[f * 2 + tid], acc);
        g_oi[win * 2 + tid] = acc;
    }
}

// GEMM mainloop, A = pre-split smem uint2 buffer
__device__ __forceinline__
void mma_main_u(const uint2* __restrict__ A, const uint4* __restrict__ wf,
                int wp, int lane, float c[4][4])
{
    const int rg = wp >> 2, cg = wp & 3;
    const int r = rg * 16 + (lane >> 2);
    const int p0 = lane & 3;
    #pragma unroll
    for (int ks = 0; ks < 8; ++ks) {
        const uint2 a0 = A[upz(r,     ks * 8 + p0)];
        const uint2 a1 = A[upz(r + 8, ks * 8 + p0)];
        const uint2 a2 = A[upz(r,     ks * 8 + 4 + p0)];
        const uint2 a3 = A[upz(r + 8, ks * 8 + 4 + p0)];
        #pragma unroll
        for (int nt = 0; nt < 4; ++nt) {
            const uint4 bf = __ldg(wf + ((cg * 4 + nt) * 8 + ks) * 32 + lane);
            mma3(c[nt], a0, a1, a2, a3, bf.x, bf.y, bf.z, bf.w);
        }
    }
}

// GEMM mainloop, A = pre-split gmem uint2 (linear [tok][p])
__device__ __forceinline__
void mma_main_ug(const uint2* __restrict__ A, const uint4* __restrict__ wf,
                 int wp, int lane, float c[4][4])
{
    const int rg = wp >> 2, cg = wp & 3;
    const int r = rg * 16 + (lane >> 2);
    const int p0 = lane & 3;
    #pragma unroll
    for (int ks = 0; ks < 8; ++ks) {
        const uint2 a0 = __ldg(A + (r    ) * 64 + ks * 8 + p0);
        const uint2 a1 = __ldg(A + (r + 8) * 64 + ks * 8 + p0);
        const uint2 a2 = __ldg(A + (r    ) * 64 + ks * 8 + 4 + p0);
        const uint2 a3 = __ldg(A + (r + 8) * 64 + ks * 8 + 4 + p0);
        #pragma unroll
        for (int nt = 0; nt < 4; ++nt) {
            const uint4 bf = __ldg(wf + ((cg * 4 + nt) * 8 + ks) * 32 + lane);
            mma3(c[nt], a0, a1, a2, a3, bf.x, bf.y, bf.z, bf.w);
        }
    }
}

// epilogue -> pre-split uint2 buffer
__device__ __forceinline__
void mma_epi_u(float c[4][4], const float* __restrict__ bias, int boff,
               uint2* __restrict__ outU, int wp, int lane)
{
    const int rg = wp >> 2, cg = wp & 3;
    const int r = rg * 16 + (lane >> 2);
    const int p0 = lane & 3;
    #pragma unroll
    for (int nt = 0; nt < 4; ++nt) {
        const int col = cg * 32 + nt * 8 + p0 * 2;
        const float2 bv = *(const float2*)(bias + boff + col);
        outU[upz(r,     col >> 1)] = split_pair(c[nt][0] + bv.x, c[nt][1] + bv.y);
        outU[upz(r + 8, col >> 1)] = split_pair(c[nt][2] + bv.x, c[nt][3] + bv.y);
    }
}

// epilogue -> f32 swz buffer (for v)
__device__ __forceinline__
void mma_epi_f(float c[4][4], const float* __restrict__ bias, int boff,
               float* __restrict__ out_s, int wp, int lane)
{
    const int rg = wp >> 2, cg = wp & 3;
    const int r = rg * 16 + (lane >> 2);
    const int q2 = (lane & 3) * 2;
    #pragma unroll
    for (int nt = 0; nt < 4; ++nt) {
        const int col = cg * 32 + nt * 8 + q2;
        const float2 bv = *(const float2*)(bias + boff + col);
        *(float2*)(out_s + swz(r,     col)) = make_float2(c[nt][0] + bv.x, c[nt][1] + bv.y);
        *(float2*)(out_s + swz(r + 8, col)) = make_float2(c[nt][2] + bv.x, c[nt][3] + bv.y);
    }
}

// ---------------- kernel 2 ----------------
__global__ __launch_bounds__(NTHR, 2)
void k_main(const float* __restrict__ rpp,
            const float* __restrict__ q_b, const float* __restrict__ kv_b,
            const float* __restrict__ o_b, float* __restrict__ out)
{
    extern __shared__ float sm[];
    float* bufX = sm;            // xd f32 -> k uint2
    float* bufY = sm + 8192;     // xd2 uint2 -> v f32 (in-place, barrier)
    float* bufZ = sm + 16384;    // q uint2 -> attn uint2 (per-head col reuse)
    float* sSim = sm + 24576;    // sim f32 (float2 slots) -> probs uint2

    uint2* XU = (uint2*)bufX;
    uint2* YU = (uint2*)bufY;
    uint2* ZU = (uint2*)bufZ;
    float2* simF2 = (float2*)sSim;
    uint2*  probU = (uint2*)sSim;

    const int win = blockIdx.x;
    const int b   = win >> 10;
    const int wr  = win & 1023;
    const int wi  = wr >> 5;
    const int wj  = wr & 31;
    const int tid = threadIdx.x;
    const int wp  = tid >> 5, tx = tid & 31;

    // ---- inter-window bilinear blend -> bufX (xd f32) ----
    {
        const float ox = __ldg(g_oi + win * 2 + 0), oy = __ldg(g_oi + win * 2 + 1);
        const float gxp = (float)wj + ox, gyp = (float)wi + oy;
        const float x0f = floorf(gxp), y0f = floorf(gyp);
        const float fx = gxp - x0f, fy = gyp - y0f;
        const int x0 = (int)x0f, y0 = (int)y0f;
        const float wgt[4] = {(1.f - fx) * (1.f - fy), fx * (1.f - fy),
                              (1.f - fx) * fy,          fx * fy};
        const float4* nb[4];
        float nww[4];
        #pragma unroll
        for (int k = 0; k < 4; ++k) {
            const int xx = x0 + (k & 1), yy = y0 + (k >> 1);
            const bool valid = (xx >= 0) && (xx < W1G) && (yy >= 0) && (yy < W1G);
            nb[k]  = (const float4*)(valid ? (g_xw + (size_t)((b << 10) + (yy << 5) + xx) * P2 * CH)
                                           : g_xw);
            nww[k] = valid ? wgt[k] : 0.f;
        }
        float4* outv4 = (float4*)bufX;
        for (int i4 = tid; i4 < 2048; i4 += NTHR) {
            const float4 v0 = __ldg(nb[0] + i4), v1 = __ldg(nb[1] + i4);
            const float4 v2 = __ldg(nb[2] + i4), v3 = __ldg(nb[3] + i4);
            float4 r;
            r.x = nww[0]*v0.x + nww[1]*v1.x + nww[2]*v2.x + nww[3]*v3.x;
            r.y = nww[0]*v0.y + nww[1]*v1.y + nww[2]*v2.y + nww[3]*v3.y;
            r.z = nww[0]*v0.z + nww[1]*v1.z + nww[2]*v2.z + nww[3]*v3.z;
            r.w = nww[0]*v0.w + nww[1]*v1.w + nww[2]*v2.w + nww[3]*v3.w;
            outv4[swz4(i4 >> 5, i4 & 31)] = r;
        }
    }
    __syncthreads();

    // ---- intra-window gather bufX -> bufY (xd2 pre-split uint2) ----
    {
        const float4* inv4 = (const float4*)bufX;
        #pragma unroll
        for (int it = 0; it < 4; ++it) {
            const int i4 = tid + it * NTHR;
            const int tok = i4 >> 5, c4 = i4 & 31;
            const int pi = tok >> 3, pj = tok & 7;
            const float o0 = __ldg(g_off + win * 128 + tok * 2);
            const float o1 = __ldg(g_off + win * 128 + tok * 2 + 1);
            const float gx2 = (float)pj + o0, gy2 = (float)pi + o1;
            const float xf = floorf(gx2), yf = floorf(gy2);
            const float fx = gx2 - xf, fy = gy2 - yf;
            const int x0 = (int)xf, y0 = (int)yf;
            const float ww[4] = {(1.f - fx) * (1.f - fy), fx * (1.f - fy),
                                 (1.f - fx) * fy,          fx * fy};
            float4 r = make_float4(0.f, 0.f, 0.f, 0.f);
            #pragma unroll
            for (int k = 0; k < 4; ++k) {
                const int xx = x0 + (k & 1), yy = y0 + (k >> 1);
                const bool valid = (xx >= 0) && (xx < WSZ) && (yy >= 0) && (yy < WSZ);
                const int idx = valid ? (yy * 8 + xx) : 0;
                const float wk = valid ? ww[k] : 0.f;
                const float4 a = inv4[swz4(idx, c4)];
                r.x = fmaf(wk, a.x, r.x);
                r.y = fmaf(wk, a.y, r.y);
                r.z = fmaf(wk, a.z, r.z);
                r.w = fmaf(wk, a.w, r.w);
            }
            YU[upz(tok, 2 * c4)]     = split_pair(r.x, r.y);
            YU[upz(tok, 2 * c4 + 1)] = split_pair(r.z, r.w);
        }
    }
    __syncthreads();

    // ---- GEMMs on tensor cores (pre-split operands) ----
    {   // k: YU(xd2) -> XU (xd dead)
        float c[4][4] = {};
        mma_main_u(YU, g_kf, wp, tx, c);
        mma_epi_u(c, kv_b, 0, XU, wp, tx);
    }
    {   // q: g_xq -> ZU
        float c[4][4] = {};
        mma_main_ug(g_xq + (size_t)win * P2 * 64, g_qf, wp, tx, c);
        mma_epi_u(c, q_b, 0, ZU, wp, tx);
    }
    {   // v: YU -> bufY f32 in-place (barrier between reads and writes)
        float c[4][4] = {};
        mma_main_u(YU, g_vf, wp, tx, c);
        __syncthreads();
        mma_epi_f(c, kv_b, 128, bufY, wp, tx);
    }
    __syncthreads();

    // ---- attention (per head: QK -> softmax -> PV), all tensor-core ----
    const float scale = 0.17677669529663687f;
    const bool lastRow = (wi == W1G - 1), lastCol = (wj == W1G - 1);
    const int rg = wp >> 2, cg = wp & 3;
    const int rA = rg * 16 + (tx >> 2);
    const int p0 = tx & 3;
    const int q2 = p0 * 2;
    const int sr0 = wp * 4;

    for (int hh = 0; hh < NH; ++hh) {
        // -- QK: sim tile 16x16 per warp. A = ZU(q), B = XU(k) --
        {
            float c[2][4] = {};
            #pragma unroll
            for (int ks = 0; ks < 2; ++ks) {
                const int chp = hh * 16 + ks * 8 + p0;
                const uint2 a0 = ZU[upz(rA,     chp)];
                const uint2 a1 = ZU[upz(rA + 8, chp)];
                const uint2 a2 = ZU[upz(rA,     chp + 4)];
                const uint2 a3 = ZU[upz(rA + 8, chp + 4)];
                #pragma unroll
                for (int nt = 0; nt < 2; ++nt) {
                    const int n = cg * 16 + nt * 8 + (tx >> 2);
                    const uint2 b0 = XU[upz(n, chp)];
                    const uint2 b1 = XU[upz(n, chp + 4)];
                    mma3(c[nt], a0, a1, a2, a3, b0.x, b1.x, b0.y, b1.y);
                }
            }
            const float* rb = rpp + hh * 225;
            #pragma unroll
            for (int nt = 0; nt < 2; ++nt) {
                const int col = cg * 16 + nt * 8 + q2;
                #pragma unroll
                for (int h2 = 0; h2 < 2; ++h2) {
                    const int i = rA + 8 * h2;
                    const int pi_i = i >> 3, pj_i = i & 7;
                    float vals[2];
                    #pragma unroll
                    for (int u = 0; u < 2; ++u) {
                        const int j = col + u;
                        const int pi_j = j >> 3, pj_j = j & 7;
                        const float bias = __ldg(rb + (pi_i - pi_j + 7) * 15 + (pj_i - pj_j + 7));
                        const bool msk = (lastRow && ((pi_i < 4) != (pi_j < 4)))
                                      || (lastCol && ((pj_i < 4) != (pj_j < 4)));
                        vals[u] = msk ? -CUDART_INF_F : fmaf(c[nt][2 * h2 + u], scale, bias);
                    }
                    simF2[psl(i, col >> 1)] = make_float2(vals[0], vals[1]);
                }
            }
        }
        __syncthreads();

        // -- softmax: warp owns rows sr0..sr0+3; slot tx holds j=2tx,2tx+1 --
        #pragma unroll
        for (int r = 0; r < 4; ++r) {
            const int i = sr0 + r;
            const float2 f = simF2[psl(i, tx)];
            float m = fmaxf(f.x, f.y);
            #pragma unroll
            for (int s2 = 16; s2 > 0; s2 >>= 1) m = fmaxf(m, __shfl_xor_sync(0xffffffffu, m, s2));
            const float e0 = __expf(f.x - m), e1 = __expf(f.y - m);
            float s = e0 + e1;
            #pragma unroll
            for (int s2 = 16; s2 > 0; s2 >>= 1) s += __shfl_xor_sync(0xffffffffu, s, s2);
            const float inv = 1.f / s;
            probU[psl(i, tx)] = split_pair(e0 * inv, e1 * inv);
        }
        __syncthreads();

        // -- PV: out tile 16x8 per warp. A = probU, B = v f32 (split here) --
        {
            float c[4] = {};
            const int nB = hh * HD + cg * 8 + (tx >> 2);
            #pragma unroll
            for (int ks = 0; ks < 4; ++ks) {
                const int kp = ks * 8 + p0;
                const uint2 a0 = probU[psl(rA,     kp)];
                const uint2 a1 = probU[psl(rA + 8, kp)];
                const uint2 a2 = probU[psl(rA,     kp + 4)];
                const uint2 a3 = probU[psl(rA + 8, kp + 4)];
                const int k0 = ks * 16;
                const float v00 = bufY[swz(k0 + q2,     nB)];
                const float v01 = bufY[swz(k0 + q2 + 1, nB)];
                const float v10 = bufY[swz(k0 + q2 + 8, nB)];
                const float v11 = bufY[swz(k0 + q2 + 9, nB)];
                const unsigned bh0 = prmt_hi(v00, v01);
                const unsigned bl0 = pack_rn(v00 - trunc_hi(v00), v01 - trunc_hi(v01));
                const unsigned bh1 = prmt_hi(v10, v11);
                const unsigned bl1 = pack_rn(v10 - trunc_hi(v10), v11 - trunc_hi(v11));
                mma3(c, a0, a1, a2, a3, bh0, bh1, bl0, bl1);
            }
            const int colO = hh * HD + cg * 8 + q2;
            ZU[upz(rA,     colO >> 1)] = split_pair(c[0], c[1]);
            ZU[upz(rA + 8, colO >> 1)] = split_pair(c[2], c[3]);
        }
        __syncthreads();
    }

    // ---- o projection (A = ZU attn-out) + un-shift scatter ----
    {
        float c[4][4] = {};
        mma_main_u(ZU, g_of, wp, tx, c);
        #pragma unroll
        for (int nt = 0; nt < 4; ++nt) {
            const int col = cg * 32 + nt * 8 + q2;
            const float2 bv = *(const float2*)(o_b + col);
            #pragma unroll
            for (int h = 0; h < 2; ++h) {
                const int tok = rA + 8 * h;
                const int pi = tok >> 3, pj = tok & 7;
                const int rr = (wi * 8 + pi + SHIFT) & 255;
                const int cc = (wj * 8 + pj + SHIFT) & 255;
                float2 o;
                o.x = c[nt][2 * h + 0] + bv.x;
                o.y = c[nt][2 * h + 1] + bv.y;
                *(float2*)(out + (size_t)((((b << 8) + rr) << 8) + cc) * CH + col) = o;
            }
        }
    }
}

extern "C" void kernel_launch(void* const* d_in, const int* in_sizes, int n_in,
                              void* d_out, int out_size)
{
    const float* x    = (const float*)d_in[0];
    const float* rpp  = (const float*)d_in[1];
    const float* wi_w = (const float*)d_in[2];
    const float* wi_b = (const float*)d_in[3];
    const float* w1_w = (const float*)d_in[4];
    const float* w1_b = (const float*)d_in[5];
    const float* w2_w = (const float*)d_in[6];
    const float* w2_b = (const float*)d_in[7];
    const float* q_w  = (const float*)d_in[8];
    const float* q_b  = (const float*)d_in[9];
    const float* kv_w = (const float*)d_in[10];
    const float* kv_b = (const float*)d_in[11];
    const float* o_w  = (const float*)d_in[12];
    const float* o_b  = (const float*)d_in[13];
    float* out = (float*)d_out;

    const size_t smem2 = (size_t)(3 * 8192 + 4096) * sizeof(float);
    cudaFuncSetAttribute(k_main, cudaFuncAttributeMaxDynamicSharedMemorySize, (int)smem2);

    k_wfrag<<<16, 256>>>(q_w, kv_w, o_w);
    k_prep<<<NWIN, 256>>>(x, wi_w, wi_b, w1_w, w1_b, w2_w, w2_b);
    k_main<<<NWIN, NTHR, smem2>>>(rpp, q_b, kv_b, o_b, out);
}

// round 15
// speedup vs baseline: 1.6677x; 1.6677x over previous
#include <cuda_runtime.h>
#include <math_constants.h>

#define WSZ    8
#define P2     64
#define CH     128
#define W1G    32
#define NWPB   1024
#define BATCH  8
#define NWIN   (BATCH*NWPB)
#define HD     32
#define NH     4
#define SHIFT  4
#define PSTR   132
#define NTHR   512

__device__ __forceinline__ int swz4(int tok, int c4) { return tok * 32 + (c4 ^ (tok & 7)); }
__device__ __forceinline__ int swz(int tok, int ch) {
    return tok * 128 + ((((ch >> 2) ^ (tok & 7))) << 2) + (ch & 3);
}

// bf16 split helpers
__device__ __forceinline__ float trunc_hi(float x) {
    return __uint_as_float(__float_as_uint(x) & 0xffff0000u);
}
__device__ __forceinline__ unsigned prmt_hi(float a, float b) {
    unsigned r;
    asm("prmt.b32 %0, %1, %2, 0x7632;" : "=r"(r)
        : "r"(__float_as_uint(a)), "r"(__float_as_uint(b)));
    return r;
}
__device__ __forceinline__ unsigned pack_rn(float a, float b) {
    unsigned r;
    asm("cvt.rn.bf16x2.f32 %0, %1, %2;" : "=r"(r) : "f"(b), "f"(a));
    return r;
}
__device__ __forceinline__ void split2(float2 f, unsigned& h, unsigned& l) {
    h = prmt_hi(f.x, f.y);
    l = pack_rn(f.x - trunc_hi(f.x), f.y - trunc_hi(f.y));
}
__device__ __forceinline__ uint2 split_pair(float x, float y) {
    uint2 u;
    u.x = prmt_hi(x, y);
    u.y = pack_rn(x - trunc_hi(x), y - trunc_hi(y));
    return u;
}
__device__ __forceinline__ void mma_bf16(float c[4], unsigned a0, unsigned a1,
                                         unsigned a2, unsigned a3,
                                         unsigned b0, unsigned b1) {
    asm volatile(
        "mma.sync.aligned.m16n8k16.row.col.f32.bf16.bf16.f32 "
        "{%0,%1,%2,%3}, {%4,%5,%6,%7}, {%8,%9}, {%0,%1,%2,%3};\n"
        : "+f"(c[0]), "+f"(c[1]), "+f"(c[2]), "+f"(c[3])
        : "r"(a0), "r"(a1), "r"(a2), "r"(a3), "r"(b0), "r"(b1));
}
__device__ __forceinline__ void mma3u(float c[4], uint2 a0, uint2 a1, uint2 a2, uint2 a3,
                                      unsigned bh0, unsigned bh1, unsigned bl0, unsigned bl1) {
    mma_bf16(c, a0.x, a1.x, a2.x, a3.x, bh0, bh1);
    mma_bf16(c, a0.y, a1.y, a2.y, a3.y, bh0, bh1);
    mma_bf16(c, a0.x, a1.x, a2.x, a3.x, bl0, bl1);
}

// ---------------- scratch ----------------
__device__ float g_xw [(size_t)NWIN * P2 * CH];
__device__ float g_off[NWIN * P2 * 2];
__device__ float g_oi [NWIN * 2];
// merged weight fragments: uint4 {bh0, bh1, bl0, bl1}, idx = (n8*8+ks)*32 + lane
__device__ uint4 g_qf[4096], g_kf[4096], g_vf[4096], g_of[4096];

// ---------------- kernel 0: weight fragment prep ----------------
__global__ __launch_bounds__(256)
void k_wfrag(const float* __restrict__ q_w, const float* __restrict__ kv_w,
             const float* __restrict__ o_w)
{
    const int i = blockIdx.x * 256 + threadIdx.x;
    const int lane = i & 31, ks = (i >> 5) & 7, n8 = i >> 8;
    const int n  = n8 * 8 + (lane >> 2);
    const int kb = ks * 16 + (lane & 3) * 2;

    #define DO_FRAG(w, S, O, f) {                                             \
        const float v00 = w[(size_t)(kb    ) * S + O + n];                    \
        const float v01 = w[(size_t)(kb + 1) * S + O + n];                    \
        const float v10 = w[(size_t)(kb + 8) * S + O + n];                    \
        const float v11 = w[(size_t)(kb + 9) * S + O + n];                    \
        f[i] = make_uint4(prmt_hi(v00, v01), prmt_hi(v10, v11),               \
                          pack_rn(v00 - trunc_hi(v00), v01 - trunc_hi(v01)),  \
                          pack_rn(v10 - trunc_hi(v10), v11 - trunc_hi(v11))); \
    }
    DO_FRAG(q_w, 128, 0,   g_qf)
    DO_FRAG(kv_w, 256, 0,   g_kf)
    DO_FRAG(kv_w, 256, 128, g_vf)
    DO_FRAG(o_w, 128, 0,   g_of)
    #undef DO_FRAG
}

// ---------------- kernel 1: window gather + offset MLPs ----------------
__global__ __launch_bounds__(256)
void k_prep(const float* __restrict__ x,
            const float* __restrict__ wi_w, const float* __restrict__ wi_b,
            const float* __restrict__ w1_w, const float* __restrict__ w1_b,
            const float* __restrict__ w2_w, const float* __restrict__ w2_b)
{
    __shared__ float sT[P2 * PSTR];
    __shared__ float sT1[P2 * 2];

    const int win = blockIdx.x;
    const int b   = win >> 10;
    const int wr  = win & 1023;
    const int wi  = wr >> 5;
    const int wj  = wr & 31;
    const int tid = threadIdx.x;

    float4* gx4 = (float4*)(g_xw + (size_t)win * P2 * CH);

    for (int i4 = tid; i4 < P2 * CH / 4; i4 += 256) {
        const int tok = i4 >> 5, c4 = i4 & 31;
        const int pi = tok >> 3, pj = tok & 7;
        const int r = (wi * 8 + pi + SHIFT) & 255;
        const int c = (wj * 8 + pj + SHIFT) & 255;
        const float4 v = *(const float4*)(x + (size_t)((((b << 8) + r) << 8) + c) * CH + c4 * 4);
        *(float4*)(sT + tok * PSTR + c4 * 4) = v;
        gx4[i4] = v;
    }
    __syncthreads();

    {
        const int kind = tid >> 7;
        const int rem  = tid & 127;
        const int tok  = rem >> 1;
        const int d    = rem & 1;
        const float* w = kind ? w1_w : wi_w;
        float acc = 0.f;
        #pragma unroll 8
        for (int ch = 0; ch < 128; ++ch)
            acc = fmaf(sT[tok * PSTR + ch], w[ch * 2 + d], acc);
        if (kind) sT1[tok * 2 + d] = acc + w1_b[d];
        else      g_off[win * 128 + tok * 2 + d] = acc + wi_b[d];
    }
    __syncthreads();

    if (tid < 2) {
        float acc = w2_b[tid];
        for (int f = 0; f < 128; ++f)
            acc = fmaf(sT1[f], w2_w[f * 2 + tid], acc);
        g_oi[win * 2 + tid] = acc;
    }
}

// ---- bf16x3 MMA mainloops for GEMMs (warp = rg x cg of 16x32 tile) ----
#define MMA_KSTEP(LD0, LD1, LD2, LD3)                                          \
    unsigned ah0, al0, ah1, al1, ah2, al2, ah3, al3;                           \
    split2(LD0, ah0, al0); split2(LD1, ah1, al1);                              \
    split2(LD2, ah2, al2); split2(LD3, ah3, al3);                              \
    _Pragma("unroll")                                                          \
    for (int nt = 0; nt < 4; ++nt) {                                           \
        const uint4 bf = __ldg(wf + ((cg * 4 + nt) * 8 + ks) * 32 + lane);     \
        mma_bf16(c[nt], ah0, ah1, ah2, ah3, bf.x, bf.y);                       \
        mma_bf16(c[nt], al0, al1, al2, al3, bf.x, bf.y);                       \
        mma_bf16(c[nt], ah0, ah1, ah2, ah3, bf.z, bf.w);                       \
    }

__device__ __forceinline__
void mma_main_smem(const float* __restrict__ A, const uint4* __restrict__ wf,
                   int wp, int lane, float c[4][4])
{
    const int rg = wp >> 2, cg = wp & 3;
    const int r = rg * 16 + (lane >> 2);
    const int q2 = (lane & 3) * 2;
    #pragma unroll
    for (int ks = 0; ks < 8; ++ks) {
        const int k0 = ks * 16;
        MMA_KSTEP(*(const float2*)(A + swz(r,     k0 + q2)),
                  *(const float2*)(A + swz(r + 8, k0 + q2)),
                  *(const float2*)(A + swz(r,     k0 + 8 + q2)),
                  *(const float2*)(A + swz(r + 8, k0 + 8 + q2)))
    }
}

__device__ __forceinline__
void mma_main_gmem(const float* __restrict__ A, const uint4* __restrict__ wf,
                   int wp, int lane, float c[4][4])
{
    const int rg = wp >> 2, cg = wp & 3;
    const int r = rg * 16 + (lane >> 2);
    const int q2 = (lane & 3) * 2;
    #pragma unroll
    for (int ks = 0; ks < 8; ++ks) {
        const int k0 = ks * 16;
        MMA_KSTEP(__ldg((const float2*)(A + (r    ) * CH + k0 + q2)),
                  __ldg((const float2*)(A + (r + 8) * CH + k0 + q2)),
                  __ldg((const float2*)(A + (r    ) * CH + k0 + 8 + q2)),
                  __ldg((const float2*)(A + (r + 8) * CH + k0 + 8 + q2)))
    }
}

__device__ __forceinline__
void mma_epi_smem(float c[4][4], const float* __restrict__ bias, int boff,
                  float* __restrict__ out_s, int wp, int lane)
{
    const int rg = wp >> 2, cg = wp & 3;
    const int r = rg * 16 + (lane >> 2);
    const int q2 = (lane & 3) * 2;
    #pragma unroll
    for (int nt = 0; nt < 4; ++nt) {
        const int col = cg * 32 + nt * 8 + q2;
        const float2 bv = *(const float2*)(bias + boff + col);
        *(float2*)(out_s + swz(r,     col)) = make_float2(c[nt][0] + bv.x, c[nt][1] + bv.y);
        *(float2*)(out_s + swz(r + 8, col)) = make_float2(c[nt][2] + bv.x, c[nt][3] + bv.y);
    }
}

// ---------------- kernel 2 ----------------
__global__ __launch_bounds__(NTHR, 2)
void k_main(const float* __restrict__ rpp,
            const float* __restrict__ q_b, const float* __restrict__ kv_b,
            const float* __restrict__ o_b, float* __restrict__ out)
{
    extern __shared__ float sm[];
    float* bufA = sm;            // q -> attn-out (in-place per warp region)
    float* bufB = bufA + 8192;   // xd2 -> v (in-place, barrier-protected)
    float* bufC = bufB + 8192;   // xd -> k

    const int win = blockIdx.x;
    const int b   = win >> 10;
    const int wr  = win & 1023;
    const int wi  = wr >> 5;
    const int wj  = wr & 31;
    const int tid = threadIdx.x;
    const int wp  = tid >> 5, tx = tid & 31;

    // ---- inter-window bilinear blend -> bufC (xd) ----
    {
        const float ox = __ldg(g_oi + win * 2 + 0), oy = __ldg(g_oi + win * 2 + 1);
        const float gxp = (float)wj + ox, gyp = (float)wi + oy;
        const float x0f = floorf(gxp), y0f = floorf(gyp);
        const float fx = gxp - x0f, fy = gyp - y0f;
        const int x0 = (int)x0f, y0 = (int)y0f;
        const float wgt[4] = {(1.f - fx) * (1.f - fy), fx * (1.f - fy),
                              (1.f - fx) * fy,          fx * fy};
        const float4* nb[4];
        float nww[4];
        #pragma unroll
        for (int k = 0; k < 4; ++k) {
            const int xx = x0 + (k & 1), yy = y0 + (k >> 1);
            const bool valid = (xx >= 0) && (xx < W1G) && (yy >= 0) && (yy < W1G);
            nb[k]  = (const float4*)(valid ? (g_xw + (size_t)((b << 10) + (yy << 5) + xx) * P2 * CH)
                                           : g_xw);
            nww[k] = valid ? wgt[k] : 0.f;
        }
        float4* outv4 = (float4*)bufC;
        for (int i4 = tid; i4 < 2048; i4 += NTHR) {
            const float4 v0 = __ldg(nb[0] + i4), v1 = __ldg(nb[1] + i4);
            const float4 v2 = __ldg(nb[2] + i4), v3 = __ldg(nb[3] + i4);
            float4 r;
            r.x = nww[0]*v0.x + nww[1]*v1.x + nww[2]*v2.x + nww[3]*v3.x;
            r.y = nww[0]*v0.y + nww[1]*v1.y + nww[2]*v2.y + nww[3]*v3.y;
            r.z = nww[0]*v0.z + nww[1]*v1.z + nww[2]*v2.z + nww[3]*v3.z;
            r.w = nww[0]*v0.w + nww[1]*v1.w + nww[2]*v2.w + nww[3]*v3.w;
            outv4[swz4(i4 >> 5, i4 & 31)] = r;
        }
    }
    __syncthreads();

    // ---- intra-window gather bufC -> bufB (xd2) ----
    {
        const float4* inv4 = (const float4*)bufC;
        float4* outv4 = (float4*)bufB;
        #pragma unroll
        for (int it = 0; it < 4; ++it) {
            const int i4 = tid + it * NTHR;
            const int tok = i4 >> 5, c4 = i4 & 31;
            const int pi = tok >> 3, pj = tok & 7;
            const float o0 = __ldg(g_off + win * 128 + tok * 2);
            const float o1 = __ldg(g_off + win * 128 + tok * 2 + 1);
            const float gx2 = (float)pj + o0, gy2 = (float)pi + o1;
            const float xf = floorf(gx2), yf = floorf(gy2);
            const float fx = gx2 - xf, fy = gy2 - yf;
            const int x0 = (int)xf, y0 = (int)yf;
            const float ww[4] = {(1.f - fx) * (1.f - fy), fx * (1.f - fy),
                                 (1.f - fx) * fy,          fx * fy};
            float4 r = make_float4(0.f, 0.f, 0.f, 0.f);
            #pragma unroll
            for (int k = 0; k < 4; ++k) {
                const int xx = x0 + (k & 1), yy = y0 + (k >> 1);
                const bool valid = (xx >= 0) && (xx < WSZ) && (yy >= 0) && (yy < WSZ);
                const int idx = valid ? (yy * 8 + xx) : 0;
                const float wk = valid ? ww[k] : 0.f;
                const float4 a = inv4[swz4(idx, c4)];
                r.x = fmaf(wk, a.x, r.x);
                r.y = fmaf(wk, a.y, r.y);
                r.z = fmaf(wk, a.z, r.z);
                r.w = fmaf(wk, a.w, r.w);
            }
            outv4[swz4(tok, c4)] = r;
        }
    }
    __syncthreads();

    // ---- GEMMs on tensor cores (bf16x3, merged uint4 weights) ----
    {   // k: bufB(xd2) -> bufC (xd dead)
        float c[4][4] = {};
        mma_main_smem(bufB, g_kf, wp, tx, c);
        mma_epi_smem(c, kv_b, 0, bufC, wp, tx);
    }
    {   // q: gmem xw -> bufA
        float c[4][4] = {};
        mma_main_gmem(g_xw + (size_t)win * P2 * CH, g_qf, wp, tx, c);
        mma_epi_smem(c, q_b, 0, bufA, wp, tx);
    }
    {   // v: bufB -> bufB in-place, block barrier between reads and writes
        float c[4][4] = {};
        mma_main_smem(bufB, g_vf, wp, tx, c);
        __syncthreads();
        mma_epi_smem(c, kv_b, 128, bufB, wp, tx);
    }
    __syncthreads();

    // ---- attention, fully register-resident per warp ----
    // warp = (head hh, row-group rg): 16 rows x 64 cols sim tile, QK -> softmax -> PV.
    // Reads q from bufA rows rg*16..+15 / ch hh*32..+31; PV writes the SAME region.
    {
        const float scale = 0.17677669529663687f;
        const bool lastRow = (wi == W1G - 1), lastCol = (wj == W1G - 1);
        const int hh = wp & 3, rg = wp >> 2;
        const int rA = rg * 16 + (tx >> 2);
        const int q2 = (tx & 3) * 2;

        // -- QK --
        float c[8][4] = {};
        #pragma unroll
        for (int ks = 0; ks < 2; ++ks) {
            const int ch0 = hh * HD + ks * 16;
            unsigned ah0, al0, ah1, al1, ah2, al2, ah3, al3;
            split2(*(const float2*)(bufA + swz(rA,     ch0 + q2)),     ah0, al0);
            split2(*(const float2*)(bufA + swz(rA + 8, ch0 + q2)),     ah1, al1);
            split2(*(const float2*)(bufA + swz(rA,     ch0 + 8 + q2)), ah2, al2);
            split2(*(const float2*)(bufA + swz(rA + 8, ch0 + 8 + q2)), ah3, al3);
            #pragma unroll
            for (int nt = 0; nt < 8; ++nt) {
                const int n = nt * 8 + (tx >> 2);
                unsigned bh0, bl0, bh1, bl1;
                split2(*(const float2*)(bufC + swz(n, ch0 + q2)),     bh0, bl0);
                split2(*(const float2*)(bufC + swz(n, ch0 + 8 + q2)), bh1, bl1);
                mma_bf16(c[nt], ah0, ah1, ah2, ah3, bh0, bh1);
                mma_bf16(c[nt], al0, al1, al2, al3, bh0, bh1);
                mma_bf16(c[nt], ah0, ah1, ah2, ah3, bl0, bl1);
            }
        }

        // -- bias + mask + scale (in-register) --
        const float* rb = rpp + hh * 225;
        #pragma unroll
        for (int nt = 0; nt < 8; ++nt) {
            #pragma unroll
            for (int h2 = 0; h2 < 2; ++h2) {
                const int i = rA + 8 * h2;
                const int pi_i = i >> 3, pj_i = i & 7;
                #pragma unroll
                for (int u = 0; u < 2; ++u) {
                    const int j = nt * 8 + q2 + u;
                    const int pi_j = j >> 3, pj_j = j & 7;
                    const float bias = __ldg(rb + (pi_i - pi_j + 7) * 15 + (pj_i - pj_j + 7));
                    const bool msk = (lastRow && ((pi_i < 4) != (pi_j < 4)))
                                  || (lastCol && ((pj_i < 4) != (pj_j < 4)));
                    c[nt][2 * h2 + u] = msk ? -CUDART_INF_F
                                            : fmaf(c[nt][2 * h2 + u], scale, bias);
                }
            }
        }

        // -- softmax in registers (rows rA and rA+8; quad reduction over lanes) --
        float m0 = -CUDART_INF_F, m1 = -CUDART_INF_F;
        #pragma unroll
        for (int nt = 0; nt < 8; ++nt) {
            m0 = fmaxf(m0, fmaxf(c[nt][0], c[nt][1]));
            m1 = fmaxf(m1, fmaxf(c[nt][2], c[nt][3]));
        }
        m0 = fmaxf(m0, __shfl_xor_sync(0xffffffffu, m0, 1));
        m0 = fmaxf(m0, __shfl_xor_sync(0xffffffffu, m0, 2));
        m1 = fmaxf(m1, __shfl_xor_sync(0xffffffffu, m1, 1));
        m1 = fmaxf(m1, __shfl_xor_sync(0xffffffffu, m1, 2));
        float s0 = 0.f, s1 = 0.f;
        #pragma unroll
        for (int nt = 0; nt < 8; ++nt) {
            c[nt][0] = __expf(c[nt][0] - m0);
            c[nt][1] = __expf(c[nt][1] - m0);
            c[nt][2] = __expf(c[nt][2] - m1);
            c[nt][3] = __expf(c[nt][3] - m1);
            s0 += c[nt][0] + c[nt][1];
            s1 += c[nt][2] + c[nt][3];
        }
        s0 += __shfl_xor_sync(0xffffffffu, s0, 1);
        s0 += __shfl_xor_sync(0xffffffffu, s0, 2);
        s1 += __shfl_xor_sync(0xffffffffu, s1, 1);
        s1 += __shfl_xor_sync(0xffffffffu, s1, 2);
        const float inv0 = 1.f / s0, inv1 = 1.f / s1;

        // -- pack probs -> PV A-fragments (C->A layout identity) --
        uint2 aF[4][4];
        #pragma unroll
        for (int ks = 0; ks < 4; ++ks) {
            aF[ks][0] = split_pair(c[2*ks][0]   * inv0, c[2*ks][1]   * inv0);
            aF[ks][1] = split_pair(c[2*ks][2]   * inv1, c[2*ks][3]   * inv1);
            aF[ks][2] = split_pair(c[2*ks+1][0] * inv0, c[2*ks+1][1] * inv0);
            aF[ks][3] = split_pair(c[2*ks+1][2] * inv1, c[2*ks+1][3] * inv1);
        }

        // -- PV: out 16 rows x 32 head-channels, write in-place into bufA --
        #pragma unroll
        for (int nt = 0; nt < 4; ++nt) {
            float c4[4] = {};
            const int nV = hh * HD + nt * 8 + (tx >> 2);
            #pragma unroll
            for (int ks = 0; ks < 4; ++ks) {
                const int k0 = ks * 16;
                const float v00 = bufB[swz(k0 + q2,     nV)];
                const float v01 = bufB[swz(k0 + q2 + 1, nV)];
                const float v10 = bufB[swz(k0 + q2 + 8, nV)];
                const float v11 = bufB[swz(k0 + q2 + 9, nV)];
                const unsigned bh0 = prmt_hi(v00, v01);
                const unsigned bl0 = pack_rn(v00 - trunc_hi(v00), v01 - trunc_hi(v01));
                const unsigned bh1 = prmt_hi(v10, v11);
                const unsigned bl1 = pack_rn(v10 - trunc_hi(v10), v11 - trunc_hi(v11));
                mma3u(c4, aF[ks][0], aF[ks][1], aF[ks][2], aF[ks][3], bh0, bh1, bl0, bl1);
            }
            const int colO = hh * HD + nt * 8 + q2;
            *(float2*)(bufA + swz(rA,     colO)) = make_float2(c4[0], c4[1]);
            *(float2*)(bufA + swz(rA + 8, colO)) = make_float2(c4[2], c4[3]);
        }
    }
    __syncthreads();

    // ---- o projection on tensor cores + un-shift scatter ----
    {
        float c[4][4] = {};
        mma_main_smem(bufA, g_of, wp, tx, c);
        const int rg = wp >> 2, cg = wp & 3;
        const int rA = rg * 16 + (tx >> 2);
        const int q2 = (tx & 3) * 2;
        #pragma unroll
        for (int nt = 0; nt < 4; ++nt) {
            const int col = cg * 32 + nt * 8 + q2;
            const float2 bv = *(const float2*)(o_b + col);
            #pragma unroll
            for (int h = 0; h < 2; ++h) {
                const int tok = rA + 8 * h;
                const int pi = tok >> 3, pj = tok & 7;
                const int rr = (wi * 8 + pi + SHIFT) & 255;
                const int cc = (wj * 8 + pj + SHIFT) & 255;
                float2 o;
                o.x = c[nt][2 * h + 0] + bv.x;
                o.y = c[nt][2 * h + 1] + bv.y;
                *(float2*)(out + (size_t)((((b << 8) + rr) << 8) + cc) * CH + col) = o;
            }
        }
    }
}

extern "C" void kernel_launch(void* const* d_in, const int* in_sizes, int n_in,
                              void* d_out, int out_size)
{
    const float* x    = (const float*)d_in[0];
    const float* rpp  = (const float*)d_in[1];
    const float* wi_w = (const float*)d_in[2];
    const float* wi_b = (const float*)d_in[3];
    const float* w1_w = (const float*)d_in[4];
    const float* w1_b = (const float*)d_in[5];
    const float* w2_w = (const float*)d_in[6];
    const float* w2_b = (const float*)d_in[7];
    const float* q_w  = (const float*)d_in[8];
    const float* q_b  = (const float*)d_in[9];
    const float* kv_w = (const float*)d_in[10];
    const float* kv_b = (const float*)d_in[11];
    const float* o_w  = (const float*)d_in[12];
    const float* o_b  = (const float*)d_in[13];
    float* out = (float*)d_out;

    const size_t smem2 = (size_t)(3 * 8192) * sizeof(float);   // 96 KB -> 2 CTAs/SM
    cudaFuncSetAttribute(k_main, cudaFuncAttributeMaxDynamicSharedMemorySize, (int)smem2);

    k_wfrag<<<16, 256>>>(q_w, kv_w, o_w);
    k_prep<<<NWIN, 256>>>(x, wi_w, wi_b, w1_w, w1_b, w2_w, w2_b);
    k_main<<<NWIN, NTHR, smem2>>>(rpp, q_b, kv_b, o_b, out);
}